// round 13
// baseline (speedup 1.0000x reference)
#include <cuda_runtime.h>
#include <cstdint>

// MQCCLayer == depthwise 3x3 conv with F=2 shared unit-norm filters.
// Normalization cancels (conv is linear); channel slice is a no-op (C*F==8).
// out[b, c*2+f, h, w] = sum_ij x[b,c,h+i-1,w+j-1] * W[f,i,j],
// W[f] = angles[f]/||angles[f]||.
//
// Converged memory-roofline frame (R12: phased smem tile, 128 thr, 8 rows/
// block, plain float4 loads/stores, warp-uniform weights in SMEM) pushed to
// 10 CTAs/SM. Unlike R10 (reg-resident weights, 13-reg deficit -> spills),
// the smem-weight frame demands only 56 regs; the 5-reg squeeze to 51 can be
// absorbed by re-reading broadcast LDS weights instead of local spills.
// smem 21KB x 10 = 209KB <= 228KB.

#define NB 32
#define NC 4
#define NH 512
#define NW 512
#define BROWS 8              // output rows per block
#define SPAD 4               // front pad so col x lives at smem idx x+SPAD
#define SROW (SPAD + NW + 4) // 520 floats per smem row

__global__ void __launch_bounds__(128, 10)
mqcc_conv(const float* __restrict__ x, const float* __restrict__ angles,
          float* __restrict__ out) {
    __shared__ float sm[(BROWS + 2) * SROW];
    __shared__ float swt[18];               // normalized weights [f][3][3]
    const int t = threadIdx.x;
    const int bc = blockIdx.y;              // b*NC + c
    const int r0 = blockIdx.x * BROWS;      // first output row of this block
    const float* __restrict__ xin = x + (size_t)bc * (NH * NW);

    // Stage BROWS+2 input rows into padded SMEM (128 thr x float4 = 512 cols).
#pragma unroll
    for (int i = 0; i < BROWS + 2; i++) {
        int gr = r0 - 1 + i;
        float4 v = make_float4(0.f, 0.f, 0.f, 0.f);
        if ((unsigned)gr < (unsigned)NH)
            v = *reinterpret_cast<const float4*>(xin + (size_t)gr * NW + 4 * t);
        *reinterpret_cast<float4*>(&sm[i * SROW + SPAD + 4 * t]) = v;
    }
    // Zero halos: 10 rows x {left idx 0..3, right idx 516..519}
    if (t < 2 * (BROWS + 2)) {
        int i = t >> 1, side = t & 1;
        *reinterpret_cast<float4*>(&sm[i * SROW + side * (SPAD + NW)]) =
            make_float4(0.f, 0.f, 0.f, 0.f);
    }

    // Normalized weights -> SMEM, computed by 2 threads while staging loads
    // are in flight. Read back by everyone via broadcast LDS.
    if (t < 2) {
        const int f = t;
        float v[9];
        float s = 0.f;
#pragma unroll
        for (int i = 0; i < 9; i++) {
            v[i] = __ldg(&angles[f * 9 + i]);
            s += v[i] * v[i];
        }
        float inv = rsqrtf(s);
        inv = inv * (1.5f - 0.5f * s * inv * inv);   // NR step
#pragma unroll
        for (int i = 0; i < 9; i++) swt[f * 9 + i] = v[i] * inv;
    }
    __syncthreads();

    // Sliding 3-row window of 6 input cols (c0-1 .. c0+4), c0 = 4t.
    float W[3][6];
    auto load_row = [&](int i, float* d) {
        const float* s = &sm[i * SROW + SPAD + 4 * t];
        float4 M = *reinterpret_cast<const float4*>(s);
        d[0] = s[-1];
        d[1] = M.x; d[2] = M.y; d[3] = M.z; d[4] = M.w;
        d[5] = s[4];
    };
    load_row(0, W[0]);
    load_row(1, W[1]);

    const int b = bc >> 2, c = bc & 3;
    float* __restrict__ o0 =
        out + ((size_t)(b * 8 + c * 2) * NH + r0) * NW + 4 * t;
    float* __restrict__ o1 = o0 + (size_t)NH * NW;

#pragma unroll
    for (int r = 0; r < BROWS; r++) {
        load_row(r + 2, W[(r + 2) % 3]);
        float a0 = 0.f, a1 = 0.f, a2 = 0.f, a3 = 0.f;   // filter 0, cols 0..3
        float b0 = 0.f, b1 = 0.f, b2 = 0.f, b3 = 0.f;   // filter 1, cols 0..3
#pragma unroll
        for (int ir = 0; ir < 3; ir++) {
            const float* Wr = W[(r + ir) % 3];
            const float* w0 = &swt[ir * 3];        // broadcast LDS
            const float* w1 = &swt[9 + ir * 3];
#pragma unroll
            for (int j = 0; j < 3; j++) {
                float f0 = w0[j], f1 = w1[j];
                a0 = fmaf(f0, Wr[j + 0], a0);
                a1 = fmaf(f0, Wr[j + 1], a1);
                a2 = fmaf(f0, Wr[j + 2], a2);
                a3 = fmaf(f0, Wr[j + 3], a3);
                b0 = fmaf(f1, Wr[j + 0], b0);
                b1 = fmaf(f1, Wr[j + 1], b1);
                b2 = fmaf(f1, Wr[j + 2], b2);
                b3 = fmaf(f1, Wr[j + 3], b3);
            }
        }
        *reinterpret_cast<float4*>(o0) = make_float4(a0, a1, a2, a3);
        *reinterpret_cast<float4*>(o1) = make_float4(b0, b1, b2, b3);
        o0 += NW;
        o1 += NW;
    }
}

extern "C" void kernel_launch(void* const* d_in, const int* in_sizes, int n_in,
                              void* d_out, int out_size) {
    const float* x = (const float*)d_in[0];        // (32, 4, 512, 512) f32
    const float* angles = (const float*)d_in[1];   // (2, 3, 3) f32
    float* out = (float*)d_out;                    // (32, 8, 512, 512) f32

    dim3 grid(NH / BROWS, NB * NC);
    mqcc_conv<<<grid, 128>>>(x, angles, out);
}

// round 14
// speedup vs baseline: 1.1012x; 1.1012x over previous
#include <cuda_runtime.h>
#include <cstdint>

// MQCCLayer == depthwise 3x3 conv with F=2 shared unit-norm filters.
// Normalization cancels (conv is linear); channel slice is a no-op (C*F==8).
// out[b, c*2+f, h, w] = sum_ij x[b,c,h+i-1,w+j-1] * W[f,i,j],
// W[f] = angles[f]/||angles[f]||.
//
// FINAL converged kernel (= R12, best measured: 63.55us bench, 57.4us
// kernel, ~7.0 TB/s effective on 402MB compulsory traffic ~= 87% of HBM
// spec). Measured design space:
//   structure: phased smem tile BEATS {wide tile, shfl-stream, cp.async
//              pipeline, persistent ring} (all 58-68us kernel)
//   loads:  plain float4 BEATS ld.global.nc.v8+evict_last (57.4 vs 59.1)
//   stores: plain float4 BEATS st.global.cs (~+2us for .cs)
//   weights: smem broadcast (regs 56) BEATS reg-resident (regs 64)
//   occupancy: 9 CTAs/SM optimal (8 -> 58.3us, 9 -> 57.4us, 10 -> spills,
//              64.3us)

#define NB 32
#define NC 4
#define NH 512
#define NW 512
#define BROWS 8              // output rows per block
#define SPAD 4               // front pad so col x lives at smem idx x+SPAD
#define SROW (SPAD + NW + 4) // 520 floats per smem row

__global__ void __launch_bounds__(128, 9)
mqcc_conv(const float* __restrict__ x, const float* __restrict__ angles,
          float* __restrict__ out) {
    __shared__ float sm[(BROWS + 2) * SROW];
    __shared__ float swt[18];               // normalized weights [f][3][3]
    const int t = threadIdx.x;
    const int bc = blockIdx.y;              // b*NC + c
    const int r0 = blockIdx.x * BROWS;      // first output row of this block
    const float* __restrict__ xin = x + (size_t)bc * (NH * NW);

    // Stage BROWS+2 input rows into padded SMEM (128 thr x float4 = 512 cols).
#pragma unroll
    for (int i = 0; i < BROWS + 2; i++) {
        int gr = r0 - 1 + i;
        float4 v = make_float4(0.f, 0.f, 0.f, 0.f);
        if ((unsigned)gr < (unsigned)NH)
            v = *reinterpret_cast<const float4*>(xin + (size_t)gr * NW + 4 * t);
        *reinterpret_cast<float4*>(&sm[i * SROW + SPAD + 4 * t]) = v;
    }
    // Zero halos: 10 rows x {left idx 0..3, right idx 516..519}
    if (t < 2 * (BROWS + 2)) {
        int i = t >> 1, side = t & 1;
        *reinterpret_cast<float4*>(&sm[i * SROW + side * (SPAD + NW)]) =
            make_float4(0.f, 0.f, 0.f, 0.f);
    }

    // Normalized weights -> SMEM, computed by 2 threads while staging loads
    // are in flight. Read back by everyone via broadcast LDS.
    if (t < 2) {
        const int f = t;
        float v[9];
        float s = 0.f;
#pragma unroll
        for (int i = 0; i < 9; i++) {
            v[i] = __ldg(&angles[f * 9 + i]);
            s += v[i] * v[i];
        }
        float inv = rsqrtf(s);
        inv = inv * (1.5f - 0.5f * s * inv * inv);   // NR step
#pragma unroll
        for (int i = 0; i < 9; i++) swt[f * 9 + i] = v[i] * inv;
    }
    __syncthreads();

    // Sliding 3-row window of 6 input cols (c0-1 .. c0+4), c0 = 4t.
    float W[3][6];
    auto load_row = [&](int i, float* d) {
        const float* s = &sm[i * SROW + SPAD + 4 * t];
        float4 M = *reinterpret_cast<const float4*>(s);
        d[0] = s[-1];
        d[1] = M.x; d[2] = M.y; d[3] = M.z; d[4] = M.w;
        d[5] = s[4];
    };
    load_row(0, W[0]);
    load_row(1, W[1]);

    const int b = bc >> 2, c = bc & 3;
    float* __restrict__ o0 =
        out + ((size_t)(b * 8 + c * 2) * NH + r0) * NW + 4 * t;
    float* __restrict__ o1 = o0 + (size_t)NH * NW;

#pragma unroll
    for (int r = 0; r < BROWS; r++) {
        load_row(r + 2, W[(r + 2) % 3]);
        float a0 = 0.f, a1 = 0.f, a2 = 0.f, a3 = 0.f;   // filter 0, cols 0..3
        float b0 = 0.f, b1 = 0.f, b2 = 0.f, b3 = 0.f;   // filter 1, cols 0..3
#pragma unroll
        for (int ir = 0; ir < 3; ir++) {
            const float* Wr = W[(r + ir) % 3];
            const float* w0 = &swt[ir * 3];        // broadcast LDS
            const float* w1 = &swt[9 + ir * 3];
#pragma unroll
            for (int j = 0; j < 3; j++) {
                float f0 = w0[j], f1 = w1[j];
                a0 = fmaf(f0, Wr[j + 0], a0);
                a1 = fmaf(f0, Wr[j + 1], a1);
                a2 = fmaf(f0, Wr[j + 2], a2);
                a3 = fmaf(f0, Wr[j + 3], a3);
                b0 = fmaf(f1, Wr[j + 0], b0);
                b1 = fmaf(f1, Wr[j + 1], b1);
                b2 = fmaf(f1, Wr[j + 2], b2);
                b3 = fmaf(f1, Wr[j + 3], b3);
            }
        }
        *reinterpret_cast<float4*>(o0) = make_float4(a0, a1, a2, a3);
        *reinterpret_cast<float4*>(o1) = make_float4(b0, b1, b2, b3);
        o0 += NW;
        o1 += NW;
    }
}

extern "C" void kernel_launch(void* const* d_in, const int* in_sizes, int n_in,
                              void* d_out, int out_size) {
    const float* x = (const float*)d_in[0];        // (32, 4, 512, 512) f32
    const float* angles = (const float*)d_in[1];   // (2, 3, 3) f32
    float* out = (float*)d_out;                    // (32, 8, 512, 512) f32

    dim3 grid(NH / BROWS, NB * NC);
    mqcc_conv<<<grid, 128>>>(x, angles, out);
}